// round 13
// baseline (speedup 1.0000x reference)
#include <cuda_runtime.h>
#include <math.h>

#define Bsz  16
#define Tlen 1024
#define Hdim 512
#define G4H  2048
#define NA   64
#define NC   64
#define NB   20
#define NBLK (NA + NC + NB)

__device__ float g_gx[(size_t)Bsz * Tlen * G4H];
__device__ float g_out0[(size_t)Bsz * Tlen * Hdim];
__device__ float g_h0buf[2][Bsz * Hdim];
__device__ float g_h1buf[2][Bsz * Hdim];
__device__ float g_gx1[4][G4H * Bsz];          // ring: [slot][row*16 + b]
__device__ unsigned int g_leafA[8 * 64], g_leafC[8 * 64];
__device__ unsigned int g_topA, g_topC, g_cntB, g_topB;

union F4U2 { float4 f; ulonglong2 u; };

__device__ __forceinline__ unsigned long long ffma2(unsigned long long a,
                                                    unsigned long long b,
                                                    unsigned long long c) {
    unsigned long long d;
    asm("fma.rn.f32x2 %0, %1, %2, %3;" : "=l"(d) : "l"(a), "l"(b), "l"(c));
    return d;
}
__device__ __forceinline__ unsigned long long dup2(float x) {
    unsigned long long r;
    asm("mov.b64 %0, {%1, %1};" : "=l"(r) : "f"(x));
    return r;
}
__device__ __forceinline__ void unpk2(unsigned long long v, float& lo, float& hi) {
    asm("mov.b64 {%0, %1}, %2;" : "=f"(lo), "=f"(hi) : "l"(v));
}
__device__ __forceinline__ unsigned int ld_acq(const unsigned int* p) {
    unsigned int v;
    asm volatile("ld.acquire.gpu.global.u32 %0, [%1];" : "=r"(v) : "l"(p) : "memory");
    return v;
}
__device__ __forceinline__ void st_rel(unsigned int* p, unsigned int v) {
    asm volatile("st.release.gpu.global.u32 [%0], %1;" :: "l"(p), "r"(v) : "memory");
}
__device__ __forceinline__ unsigned int atom_add_ar(unsigned int* p) {
    unsigned int old;
    asm volatile("atom.acq_rel.gpu.global.add.u32 %0, [%1], 1;"
                 : "=r"(old) : "l"(p) : "memory");
    return old;
}
__device__ __forceinline__ void arrive_tree(unsigned int* leaf, unsigned int* top,
                                            unsigned int target8) {
    unsigned int old = atom_add_ar(leaf);
    if (old == target8 - 1u)
        asm volatile("red.release.gpu.global.add.u32 [%0], 1;" :: "l"(top) : "memory");
}
__device__ __forceinline__ void cp16(unsigned int smem_dst, const void* gsrc) {
    asm volatile("cp.async.cg.shared.global [%0], [%1], 16;"
                 :: "r"(smem_dst), "l"(gsrc) : "memory");
}
#define CP_COMMIT() asm volatile("cp.async.commit_group;" ::: "memory")
#define CP_WAIT0()  asm volatile("cp.async.wait_group 0;" ::: "memory")
#define CP_WAIT1()  asm volatile("cp.async.wait_group 1;" ::: "memory")

__device__ __forceinline__ float sigm_(float x) {
    return __fdividef(1.0f, 1.0f + __expf(-x));
}
__device__ __forceinline__ float tanh_(float x) {
    float e = __expf(2.0f * fminf(fmaxf(x, -9.0f), 9.0f));
    return __fdividef(e - 1.0f, e + 1.0f);
}

// ---------------- GEMM (NT) + sync reset ----------------
#define GP 132
__global__ __launch_bounds__(256, 2) void gemm_nt_bias(
    const float* __restrict__ A, const float* __restrict__ B,
    const float* __restrict__ bias, float* __restrict__ C,
    int M, int N, int K)
{
    if (blockIdx.x == 0 && blockIdx.y == 0 && threadIdx.x < 8) {
        g_leafA[threadIdx.x * 64] = 0u;
        g_leafC[threadIdx.x * 64] = 0u;
        if (threadIdx.x == 0) { g_topA = 0u; g_topC = 0u; g_cntB = 0u; g_topB = 0u; }
    }
    __shared__ float As[32][GP];
    __shared__ float Bs[32][GP];
    const int tid = threadIdx.x;
    const int m0 = blockIdx.y * 128, n0 = blockIdx.x * 128;
    const int tx = tid & 15, ty = tid >> 4;
    const int lrow = tid >> 3, lkq = tid & 7;

    unsigned long long acc[8][4];
#pragma unroll
    for (int i = 0; i < 8; i++)
#pragma unroll
        for (int j = 0; j < 4; j++) acc[i][j] = 0ull;

    for (int k0 = 0; k0 < K; k0 += 32) {
#pragma unroll
        for (int i = 0; i < 4; i++) {
            int row = lrow + 32 * i;
            float4 va = *(const float4*)&A[(size_t)(m0 + row) * K + k0 + lkq * 4];
            As[lkq * 4 + 0][row] = va.x; As[lkq * 4 + 1][row] = va.y;
            As[lkq * 4 + 2][row] = va.z; As[lkq * 4 + 3][row] = va.w;
            float4 vb = *(const float4*)&B[(size_t)(n0 + row) * K + k0 + lkq * 4];
            Bs[lkq * 4 + 0][row] = vb.x; Bs[lkq * 4 + 1][row] = vb.y;
            Bs[lkq * 4 + 2][row] = vb.z; Bs[lkq * 4 + 3][row] = vb.w;
        }
        __syncthreads();
#pragma unroll
        for (int k = 0; k < 32; k++) {
            float4 a0 = *(const float4*)&As[k][ty * 8];
            float4 a1 = *(const float4*)&As[k][ty * 8 + 4];
            F4U2 b0, b1;
            b0.f = *(const float4*)&Bs[k][tx * 8];
            b1.f = *(const float4*)&Bs[k][tx * 8 + 4];
            unsigned long long bb[4] = { b0.u.x, b0.u.y, b1.u.x, b1.u.y };
            float av[8] = { a0.x, a0.y, a0.z, a0.w, a1.x, a1.y, a1.z, a1.w };
#pragma unroll
            for (int i = 0; i < 8; i++) {
                unsigned long long a2 = dup2(av[i]);
#pragma unroll
                for (int j = 0; j < 4; j++) acc[i][j] = ffma2(a2, bb[j], acc[i][j]);
            }
        }
        __syncthreads();
    }
    float bv[8];
    {
        float4 t0 = *(const float4*)&bias[n0 + tx * 8];
        float4 t1 = *(const float4*)&bias[n0 + tx * 8 + 4];
        bv[0]=t0.x; bv[1]=t0.y; bv[2]=t0.z; bv[3]=t0.w;
        bv[4]=t1.x; bv[5]=t1.y; bv[6]=t1.z; bv[7]=t1.w;
    }
#pragma unroll
    for (int i = 0; i < 8; i++) {
        int row = m0 + ty * 8 + i;
        float v[8];
#pragma unroll
        for (int j = 0; j < 4; j++) unpk2(acc[i][j], v[2 * j], v[2 * j + 1]);
        *(float4*)&C[(size_t)row * N + n0 + tx * 8] =
            make_float4(v[0]+bv[0], v[1]+bv[1], v[2]+bv[2], v[3]+bv[3]);
        *(float4*)&C[(size_t)row * N + n0 + tx * 8 + 4] =
            make_float4(v[4]+bv[4], v[5]+bv[5], v[6]+bv[6], v[7]+bv[7]);
    }
}

// ---------------- Fused tri-group pipelined scan ----------------
// C smem layout (floats): wih 8192 | h 8704 | ow 4608 | part 10368 | gxs 576
//                         | c 128 | bias 32  = 32608  (pad to 32640)
#define SCAN_SMEM (32640 * 4)

__global__ __launch_bounds__(256, 1) void lstm_fused(
    const float* __restrict__ gx,
    const float* __restrict__ w_hh0, const float* __restrict__ b_hh0,
    const float* __restrict__ w_ih1, const float* __restrict__ w_hh1,
    const float* __restrict__ b_ih1, const float* __restrict__ b_hh1,
    const float* __restrict__ h0, const float* __restrict__ c0,
    float* __restrict__ out)
{
    extern __shared__ float smem[];
    const int tid = threadIdx.x, lane = tid & 31;
    const int kwid = tid >> 5, ksl = lane >> 4, rslot = lane & 15;

    // ================= GROUP B: streamed half-ih GEMM =================
    if (blockIdx.x >= NA + NC) {
        const int gb = blockIdx.x - (NA + NC);
        const int r0 = gb * 102 + (gb < 8 ? gb : 8);
        const int r1 = r0 + 102 + (gb < 8 ? 1 : 0);
        float* o_s = smem;                       // 16 * 260
        float* wb  = o_s + 4160;                 // 2 * 4096
        const unsigned int o_sm = (unsigned int)__cvta_generic_to_shared(o_s);
        const unsigned int w_sm = (unsigned int)__cvta_generic_to_shared(wb);
        const int rl = tid >> 4, b2 = tid & 15;

        for (int t = 0; t < Tlen; t++) {
            if (tid == 0) {
                while (ld_acq(&g_topA) < 8u * (unsigned)(t + 1)) { }
                if (t >= 4) while (ld_acq(&g_topC) < 8u * (unsigned)(t - 3)) { }
            }
            __syncthreads();
            // stage out0[t][*, 256:512) + W chunk 0
#pragma unroll
            for (int i = 0; i < 4; i++) {
                int idx = tid + 256 * i, b = idx >> 6, q = idx & 63;
                cp16(o_sm + (b * 260 + q * 4) * 4,
                     &g_out0[(size_t)(b * Tlen + t) * Hdim + 256 + q * 4]);
            }
#pragma unroll
            for (int i = 0; i < 4; i++) {
                int idx = tid + 256 * i, r = idx >> 6, q = idx & 63;
                int row = r0 + r; if (row > r1 - 1) row = r1 - 1;
                cp16(w_sm + (r * 256 + q * 4) * 4,
                     &w_ih1[(size_t)row * Hdim + 256 + q * 4]);
            }
            CP_COMMIT();
            float* ring = g_gx1[t & 3];
            for (int ch = 0; ch < 7; ch++) {
                if (ch + 1 < 7) {
#pragma unroll
                    for (int i = 0; i < 4; i++) {
                        int idx = tid + 256 * i, r = idx >> 6, q = idx & 63;
                        int row = r0 + (ch + 1) * 16 + r; if (row > r1 - 1) row = r1 - 1;
                        cp16(w_sm + (((ch + 1) & 1) * 4096 + r * 256 + q * 4) * 4,
                             &w_ih1[(size_t)row * Hdim + 256 + q * 4]);
                    }
                    CP_COMMIT();
                    CP_WAIT1();
                } else CP_WAIT0();
                __syncthreads();
                int row = r0 + ch * 16 + rl;
                if (row < r1) {
                    unsigned long long a0 = 0, a1 = 0;
                    const float* wr = wb + (ch & 1) * 4096 + rl * 256;
                    const float* orow = o_s + b2 * 260;
#pragma unroll 16
                    for (int q = 0; q < 64; q++) {
                        F4U2 w4, o4;
                        w4.f = *(const float4*)&wr[q * 4];
                        o4.f = *(const float4*)&orow[q * 4];
                        a0 = ffma2(w4.u.x, o4.u.x, a0);
                        a1 = ffma2(w4.u.y, o4.u.y, a1);
                    }
                    float lo, hi, l2, h2;
                    unpk2(a0, lo, hi); unpk2(a1, l2, h2);
                    __stcg(&ring[row * 16 + b2], (lo + hi) + (l2 + h2));
                }
                __syncthreads();
            }
            if (tid == 0) {
                unsigned int old = atom_add_ar(&g_cntB);
                if (old == (unsigned)NB * (t + 1) - 1u)
                    st_rel(&g_topB, (unsigned)(t + 1));
            }
        }
        return;
    }

    // ================= GROUPS A / C =================
    const bool isA = (blockIdx.x < NA);
    const int gbid = isA ? blockIdx.x : blockIdx.x - NA;
    const int jb = gbid * 8;
    unsigned int* myLeaf = (isA ? g_leafA : g_leafC) + (gbid & 7) * 64;
    unsigned int* myTop  = isA ? &g_topA : &g_topC;

    float* wih_s  = smem;                          // C only: 8192
    float* h_all  = isA ? smem : wih_s + 8192;     // 8704
    float* ow_all = h_all + 8704;                  // C only: 4608
    float* part   = (isA ? h_all : ow_all) + (isA ? 8704 : 4608);
    float* gxs    = part + 10368;                  // 576
    float* c_s    = gxs + 576;
    float* bias_s = c_s + 128;
    float* hw = h_all + kwid * 1088;               // [16 b][64 k] pitch 68
    float* ow = ow_all + kwid * 576;               // C: [16 b][32 k] pitch 36

    const float* whh = isA ? w_hh0 : w_hh1;
    unsigned long long w0[16], w1[16];
    {
        const int g0 = (rslot >> 3) * Hdim + jb + (rslot & 7);
        const int g1 = ((rslot + 16) >> 3) * Hdim + jb + ((rslot + 16) & 7);
        const float* p0 = &whh[(size_t)g0 * Hdim + kwid * 64 + ksl * 32];
        const float* p1 = &whh[(size_t)g1 * Hdim + kwid * 64 + ksl * 32];
#pragma unroll
        for (int kp = 0; kp < 8; kp++) {
            F4U2 a; a.f = *(const float4*)&p0[kp * 4];
            w0[2 * kp] = a.u.x; w0[2 * kp + 1] = a.u.y;
            F4U2 b; b.f = *(const float4*)&p1[kp * 4];
            w1[2 * kp] = b.u.x; w1[2 * kp + 1] = b.u.y;
        }
    }
    if (!isA) {  // W_ih1 lower half (k<256): [(kq*32+row)*4], kq 0..63
#pragma unroll
        for (int i = 0; i < 8; i++) {
            int idx = tid + 256 * i, kq = idx >> 5, row = idx & 31;
            int grow = (row >> 3) * Hdim + jb + (row & 7);
            *(float4*)&wih_s[(size_t)(kq * 32 + row) * 4] =
                *(const float4*)&w_ih1[(size_t)grow * Hdim + kq * 4];
        }
    }
    if (tid < 32) {
        int grow = (tid >> 3) * Hdim + jb + (tid & 7);
        bias_s[tid] = isA ? b_hh0[grow] : (b_ih1[grow] + b_hh1[grow]);
    }
    if (tid < 128) {
        int jj = tid >> 4, b = tid & 15;
        c_s[tid] = c0[(isA ? 0 : Bsz * Hdim) + b * Hdim + jb + jj];
    }
    __syncthreads();

    float4 gxv = make_float4(0.f, 0.f, 0.f, 0.f);
    if (isA && tid < 128) {
        int b = tid >> 3, g = (tid >> 1) & 3, hf = tid & 1;
        gxv = __ldcg((const float4*)&gx[(size_t)(b * Tlen) * G4H + g * Hdim + jb + hf * 4]);
    }
    if (!isA) {  // prologue: stage ow(0) lower half, per warp
        if (lane == 0) while (ld_acq(&g_topA) < 8u) { }
        __syncwarp();
#pragma unroll
        for (int i = 0; i < 4; i++) {
            int idx = lane + 32 * i, b = idx >> 3, q = idx & 7;
            float4 o = __ldcg((const float4*)&g_out0[(size_t)(b * Tlen) * Hdim + kwid * 32 + q * 4]);
            *(float4*)&ow[b * 36 + q * 4] = o;
        }
        __syncwarp();
    }

    for (int t = 0; t < Tlen; t++) {
        unsigned long long acc0[16], acc1[16];
#pragma unroll
        for (int b = 0; b < 16; b++) { acc0[b] = 0ull; acc1[b] = 0ull; }

        if (!isA) {  // half ih dot first (hides barrier settle)
#pragma unroll
            for (int kp = 0; kp < 4; kp++) {
                const int kq = kwid * 8 + ksl * 4 + kp;
                F4U2 wa; wa.f = *(const float4*)&wih_s[(size_t)(kq * 32 + rslot) * 4];
                F4U2 wb; wb.f = *(const float4*)&wih_s[(size_t)(kq * 32 + rslot + 16) * 4];
#pragma unroll
                for (int b = 0; b < 16; b++) {
                    F4U2 o4; o4.f = *(const float4*)&ow[b * 36 + (ksl * 4 + kp) * 4];
                    acc0[b] = ffma2(wa.u.x, o4.u.x, acc0[b]);
                    acc0[b] = ffma2(wa.u.y, o4.u.y, acc0[b]);
                    acc1[b] = ffma2(wb.u.x, o4.u.x, acc1[b]);
                    acc1[b] = ffma2(wb.u.y, o4.u.y, acc1[b]);
                }
            }
            // ring gx (B's half), warps 0-3 only
            if (kwid < 4) {
                if (lane == 0) while (ld_acq(&g_topB) < (unsigned)(t + 1)) { }
                __syncwarp();
                int rlcl = tid >> 2, bq = tid & 3;
                int grow2 = (rlcl >> 3) * Hdim + jb + (rlcl & 7);
                gxv = __ldcg((const float4*)&g_gx1[t & 3][grow2 * 16 + bq * 4]);
            }
        }

        // own-group gate + stage h (per warp)
        if (lane == 0 && t > 0) while (ld_acq(myTop) < 8u * (unsigned)t) { }
        __syncwarp();
        const float* hsrc = isA
            ? ((t == 0) ? h0 : g_h0buf[t & 1])
            : ((t == 0) ? h0 + Bsz * Hdim : g_h1buf[t & 1]);
#pragma unroll
        for (int i = 0; i < 8; i++) {
            int idx = lane + 32 * i, b = idx >> 4, q = idx & 15;
            float4 v = __ldcg((const float4*)&hsrc[b * Hdim + kwid * 64 + q * 4]);
            *(float4*)&hw[b * 68 + q * 4] = v;
        }
        __syncwarp();

        // hh dot
#pragma unroll
        for (int kp = 0; kp < 8; kp++) {
#pragma unroll
            for (int b = 0; b < 16; b++) {
                F4U2 h4; h4.f = *(const float4*)&hw[b * 68 + ksl * 32 + kp * 4];
                acc0[b] = ffma2(w0[2 * kp],     h4.u.x, acc0[b]);
                acc0[b] = ffma2(w0[2 * kp + 1], h4.u.y, acc0[b]);
                acc1[b] = ffma2(w1[2 * kp],     h4.u.x, acc1[b]);
                acc1[b] = ffma2(w1[2 * kp + 1], h4.u.y, acc1[b]);
            }
        }
        // partials
        {
            const int ks = kwid * 2 + ksl;
            float v0[16], v1[16];
#pragma unroll
            for (int b = 0; b < 16; b++) {
                float lo, hi;
                unpk2(acc0[b], lo, hi); v0[b] = lo + hi;
                unpk2(acc1[b], lo, hi); v1[b] = lo + hi;
            }
            float4* p0 = (float4*)&part[ks * 648 + rslot * 20];
            float4* p1 = (float4*)&part[ks * 648 + (rslot + 16) * 20];
#pragma unroll
            for (int j = 0; j < 4; j++) {
                p0[j] = make_float4(v0[4*j], v0[4*j+1], v0[4*j+2], v0[4*j+3]);
                p1[j] = make_float4(v1[4*j], v1[4*j+1], v1[4*j+2], v1[4*j+3]);
            }
        }
        if (tid < 128) {
            if (isA) {
                int b = tid >> 3, g = (tid >> 1) & 3, hf = tid & 1;
                *(float4*)&gxs[b * 36 + g * 8 + hf * 4] = gxv;
            } else {
                *(float4*)&gxs[(tid >> 2) * 16 + (tid & 3) * 4] = gxv;
            }
        }
        __syncthreads();

        // cell (warps 0-3): reduce folded in
        if (tid < 128) {
            int jj = tid >> 4, b = tid & 15;
            float vi = 0.f, vf = 0.f, vg = 0.f, vo = 0.f;
#pragma unroll
            for (int k2 = 0; k2 < 16; k2++) {
                const float* pk = &part[k2 * 648 + b];
                vi += pk[(0  + jj) * 20];
                vf += pk[(8  + jj) * 20];
                vg += pk[(16 + jj) * 20];
                vo += pk[(24 + jj) * 20];
            }
            vi += bias_s[jj];      vf += bias_s[8 + jj];
            vg += bias_s[16 + jj]; vo += bias_s[24 + jj];
            if (isA) {
                vi += gxs[b * 36 + jj];       vf += gxs[b * 36 + 8 + jj];
                vg += gxs[b * 36 + 16 + jj];  vo += gxs[b * 36 + 24 + jj];
            } else {
                vi += gxs[(0  + jj) * 16 + b];
                vf += gxs[(8  + jj) * 16 + b];
                vg += gxs[(16 + jj) * 16 + b];
                vo += gxs[(24 + jj) * 16 + b];
            }
            float ig = sigm_(vi), fg = sigm_(vf);
            float gg = tanh_(vg), og = sigm_(vo);
            float c = fg * c_s[tid] + ig * gg;
            c_s[tid] = c;
            float h = og * tanh_(c);
            int col = jb + jj;
            if (isA) {
                __stcg(&g_h0buf[(t + 1) & 1][b * Hdim + col], h);
                __stcg(&g_out0[(size_t)(b * Tlen + t) * Hdim + col], h);
                if (t == Tlen - 1) out[b * Hdim + col] = h;
            } else {
                __stcg(&g_h1buf[(t + 1) & 1][b * Hdim + col], h);
                if (t == Tlen - 1) out[Bsz * Hdim + b * Hdim + col] = h;
            }
        }
        // next-step prefetches
        if (isA) {
            if (tid < 128 && t + 1 < Tlen) {
                int b = tid >> 3, g = (tid >> 1) & 3, hf = tid & 1;
                gxv = __ldcg((const float4*)&gx[(size_t)(b * Tlen + t + 1) * G4H + g * Hdim + jb + hf * 4]);
            }
        } else if (t + 1 < Tlen) {  // stage ow(t+1) lower half, per warp
            if (lane == 0) while (ld_acq(&g_topA) < 8u * (unsigned)(t + 2)) { }
            __syncwarp();
#pragma unroll
            for (int i = 0; i < 4; i++) {
                int idx = lane + 32 * i, b = idx >> 3, q = idx & 7;
                float4 o = __ldcg((const float4*)&g_out0[(size_t)(b * Tlen + t + 1) * Hdim + kwid * 32 + q * 4]);
                *(float4*)&ow[b * 36 + q * 4] = o;
            }
        }
        __syncthreads();

        if (tid == 0 && (isA || t < Tlen - 1))
            arrive_tree(myLeaf, myTop, 8u * (unsigned)(t + 1));
    }
}

// ---------------------------------------------------------------------------
extern "C" void kernel_launch(void* const* d_in, const int* in_sizes, int n_in,
                              void* d_out, int out_size)
{
    const float* x     = (const float*)d_in[0];
    const float* h0    = (const float*)d_in[1];
    const float* c0    = (const float*)d_in[2];
    const float* w_ih0 = (const float*)d_in[3];
    const float* w_hh0 = (const float*)d_in[4];
    const float* b_ih0 = (const float*)d_in[5];
    const float* b_hh0 = (const float*)d_in[6];
    const float* w_ih1 = (const float*)d_in[7];
    const float* w_hh1 = (const float*)d_in[8];
    const float* b_ih1 = (const float*)d_in[9];
    const float* b_hh1 = (const float*)d_in[10];
    float* out = (float*)d_out;

    void* p;
    cudaGetSymbolAddress(&p, g_gx);
    float* gx = (float*)p;

    cudaFuncSetAttribute(lstm_fused, cudaFuncAttributeMaxDynamicSharedMemorySize,
                         SCAN_SMEM);

    const int M = Bsz * Tlen;
    dim3 ggrid(G4H / 128, M / 128);
    gemm_nt_bias<<<ggrid, 256>>>(x, w_ih0, b_ih0, gx, M, G4H, Hdim);
    lstm_fused<<<NBLK, 256, SCAN_SMEM>>>(gx, w_hh0, b_hh0,
                                         w_ih1, w_hh1, b_ih1, b_hh1,
                                         h0, c0, out);
}

// round 14
// speedup vs baseline: 2.6794x; 2.6794x over previous
#include <cuda_runtime.h>
#include <math.h>

#define Bsz  16
#define Tlen 1024
#define Hdim 512
#define NA   64
#define NC   64
#define NBLK (NA + NC)

__device__ float g_out0[(size_t)Bsz * Tlen * Hdim];
__device__ float g_h0buf[2][Bsz * Hdim];
__device__ float g_h1buf[2][Bsz * Hdim];
__device__ unsigned int g_leafA[8 * 64], g_leafC[8 * 64];
__device__ unsigned int g_topA, g_topC;

union F4U2 { float4 f; ulonglong2 u; };

__device__ __forceinline__ unsigned long long ffma2(unsigned long long a,
                                                    unsigned long long b,
                                                    unsigned long long c) {
    unsigned long long d;
    asm("fma.rn.f32x2 %0, %1, %2, %3;" : "=l"(d) : "l"(a), "l"(b), "l"(c));
    return d;
}
__device__ __forceinline__ void unpk2(unsigned long long v, float& lo, float& hi) {
    asm("mov.b64 {%0, %1}, %2;" : "=f"(lo), "=f"(hi) : "l"(v));
}
__device__ __forceinline__ unsigned int ld_acq(const unsigned int* p) {
    unsigned int v;
    asm volatile("ld.acquire.gpu.global.u32 %0, [%1];" : "=r"(v) : "l"(p) : "memory");
    return v;
}
__device__ __forceinline__ void arrive_tree(unsigned int* leaf, unsigned int* top,
                                            unsigned int target8) {
    unsigned int old;
    asm volatile("atom.acq_rel.gpu.global.add.u32 %0, [%1], 1;"
                 : "=r"(old) : "l"(leaf) : "memory");
    if (old == target8 - 1u)
        asm volatile("red.release.gpu.global.add.u32 [%0], 1;" :: "l"(top) : "memory");
}
__device__ __forceinline__ float sigm_(float x) {
    return __fdividef(1.0f, 1.0f + __expf(-x));
}
__device__ __forceinline__ float tanh_(float x) {
    float e = __expf(2.0f * fminf(fmaxf(x, -9.0f), 9.0f));
    return __fdividef(e - 1.0f, e + 1.0f);
}

__global__ void reset_sync() {
    if (threadIdx.x < 8) { g_leafA[threadIdx.x * 64] = 0u; g_leafC[threadIdx.x * 64] = 0u; }
    if (threadIdx.x == 0) { g_topA = 0u; g_topC = 0u; }
}

// ---------------- Fused dual-layer scan; both layers compute ih on the fly ----
// smem floats: wih 16384 | h 8704 | iw 8704 | part 10368 | c 128 | bias 32 = 44320
#define SCAN_SMEM (44320 * 4)

__global__ __launch_bounds__(256, 1) void lstm_fused(
    const float* __restrict__ x,       // (B, T, 512)
    const float* __restrict__ w_ih0, const float* __restrict__ w_hh0,
    const float* __restrict__ b_ih0, const float* __restrict__ b_hh0,
    const float* __restrict__ w_ih1, const float* __restrict__ w_hh1,
    const float* __restrict__ b_ih1, const float* __restrict__ b_hh1,
    const float* __restrict__ h0, const float* __restrict__ c0,
    float* __restrict__ out)
{
    extern __shared__ float smem[];
    const int tid = threadIdx.x, lane = tid & 31;
    const int kwid = tid >> 5, ksl = lane >> 4, rslot = lane & 15;
    const bool isA = (blockIdx.x < NA);
    const int gbid = isA ? blockIdx.x : blockIdx.x - NA;
    const int jb = gbid * 8;
    unsigned int* myLeaf = (isA ? g_leafA : g_leafC) + (gbid & 7) * 64;
    unsigned int* myTop  = isA ? &g_topA : &g_topC;

    float* wih_s  = smem;                   // 16384
    float* h_all  = wih_s + 16384;          // 8704
    float* iw_all = h_all + 8704;           // 8704 (x for A, out0 for C)
    float* part   = iw_all + 8704;          // 10368
    float* c_s    = part + 10368;           // 128
    float* bias_s = c_s + 128;              // 32
    float* hw = h_all + kwid * 1088;        // [16 b][64 k] pitch 68
    float* iw = iw_all + kwid * 1088;

    // per-group pointers
    const float* whh  = isA ? w_hh0 : w_hh1;
    const float* wih  = isA ? w_ih0 : w_ih1;
    const float* bih  = isA ? b_ih0 : b_ih1;
    const float* bhh  = isA ? b_hh0 : b_hh1;
    const float* isrc = isA ? x : (const float*)g_out0;   // [b*Tlen+t][512]
    float (*hbuf)[Bsz * Hdim] = isA ? g_h0buf : g_h1buf;
    const int lo = isA ? 0 : Bsz * Hdim;

    // W_hh slice into registers (rows rslot, rslot+16)
    unsigned long long w0[16], w1[16];
    {
        const int g0 = (rslot >> 3) * Hdim + jb + (rslot & 7);
        const int g1 = ((rslot + 16) >> 3) * Hdim + jb + ((rslot + 16) & 7);
        const float* p0 = &whh[(size_t)g0 * Hdim + kwid * 64 + ksl * 32];
        const float* p1 = &whh[(size_t)g1 * Hdim + kwid * 64 + ksl * 32];
#pragma unroll
        for (int kp = 0; kp < 8; kp++) {
            F4U2 a; a.f = *(const float4*)&p0[kp * 4];
            w0[2 * kp] = a.u.x; w0[2 * kp + 1] = a.u.y;
            F4U2 b; b.f = *(const float4*)&p1[kp * 4];
            w1[2 * kp] = b.u.x; w1[2 * kp + 1] = b.u.y;
        }
    }
    // W_ih slice into smem: [(kq*32+row)*4], kq 0..127
#pragma unroll
    for (int i = 0; i < 16; i++) {
        int idx = tid + 256 * i, kq = idx >> 5, row = idx & 31;
        int grow = (row >> 3) * Hdim + jb + (row & 7);
        *(float4*)&wih_s[(size_t)(kq * 32 + row) * 4] =
            *(const float4*)&wih[(size_t)grow * Hdim + kq * 4];
    }
    if (tid < 32) {
        int grow = (tid >> 3) * Hdim + jb + (tid & 7);
        bias_s[tid] = bih[grow] + bhh[grow];
    }
    if (tid < 128) {
        int jj = tid >> 4, b = tid & 15;
        c_s[tid] = c0[lo + b * Hdim + jb + jj];
    }
    __syncthreads();

    // prologue: stage iw(0) (A: x[0], no wait; C: out0[0] after A step 0)
    if (!isA) {
        if (lane == 0) while (ld_acq(&g_topA) < 8u) { }
        __syncwarp();
    }
#pragma unroll
    for (int i = 0; i < 8; i++) {
        int idx = lane + 32 * i, b = idx >> 4, q = idx & 15;
        float4 v = __ldcg((const float4*)&isrc[(size_t)(b * Tlen) * Hdim + kwid * 64 + q * 4]);
        *(float4*)&iw[b * 68 + q * 4] = v;
    }
    __syncwarp();

    for (int t = 0; t < Tlen; t++) {
        unsigned long long acc0[16], acc1[16];
#pragma unroll
        for (int b = 0; b < 16; b++) { acc0[b] = 0ull; acc1[b] = 0ull; }

        // ih dot on staged iw (hides own-group barrier settle)
#pragma unroll
        for (int kp = 0; kp < 8; kp++) {
            const int kq = kwid * 16 + ksl * 8 + kp;
            F4U2 wa; wa.f = *(const float4*)&wih_s[(size_t)(kq * 32 + rslot) * 4];
            F4U2 wb; wb.f = *(const float4*)&wih_s[(size_t)(kq * 32 + rslot + 16) * 4];
#pragma unroll
            for (int b = 0; b < 16; b++) {
                F4U2 o4; o4.f = *(const float4*)&iw[b * 68 + ksl * 32 + kp * 4];
                acc0[b] = ffma2(wa.u.x, o4.u.x, acc0[b]);
                acc0[b] = ffma2(wa.u.y, o4.u.y, acc0[b]);
                acc1[b] = ffma2(wb.u.x, o4.u.x, acc1[b]);
                acc1[b] = ffma2(wb.u.y, o4.u.y, acc1[b]);
            }
        }

        // own-group gate + stage h (per warp)
        if (lane == 0 && t > 0) while (ld_acq(myTop) < 8u * (unsigned)t) { }
        __syncwarp();
        const float* hsrc = (t == 0) ? (h0 + lo) : hbuf[t & 1];
#pragma unroll
        for (int i = 0; i < 8; i++) {
            int idx = lane + 32 * i, b = idx >> 4, q = idx & 15;
            float4 v = __ldcg((const float4*)&hsrc[b * Hdim + kwid * 64 + q * 4]);
            *(float4*)&hw[b * 68 + q * 4] = v;
        }
        __syncwarp();

        // hh dot
#pragma unroll
        for (int kp = 0; kp < 8; kp++) {
#pragma unroll
            for (int b = 0; b < 16; b++) {
                F4U2 h4; h4.f = *(const float4*)&hw[b * 68 + ksl * 32 + kp * 4];
                acc0[b] = ffma2(w0[2 * kp],     h4.u.x, acc0[b]);
                acc0[b] = ffma2(w0[2 * kp + 1], h4.u.y, acc0[b]);
                acc1[b] = ffma2(w1[2 * kp],     h4.u.x, acc1[b]);
                acc1[b] = ffma2(w1[2 * kp + 1], h4.u.y, acc1[b]);
            }
        }
        // partials
        {
            const int ks = kwid * 2 + ksl;
            float v0[16], v1[16];
#pragma unroll
            for (int b = 0; b < 16; b++) {
                float plo, phi;
                unpk2(acc0[b], plo, phi); v0[b] = plo + phi;
                unpk2(acc1[b], plo, phi); v1[b] = plo + phi;
            }
            float4* p0 = (float4*)&part[ks * 648 + rslot * 20];
            float4* p1 = (float4*)&part[ks * 648 + (rslot + 16) * 20];
#pragma unroll
            for (int j = 0; j < 4; j++) {
                p0[j] = make_float4(v0[4*j], v0[4*j+1], v0[4*j+2], v0[4*j+3]);
                p1[j] = make_float4(v1[4*j], v1[4*j+1], v1[4*j+2], v1[4*j+3]);
            }
        }
        __syncthreads();

        // cell (warps 0-3): reduce folded in
        if (tid < 128) {
            int jj = tid >> 4, b = tid & 15;
            float vi = 0.f, vf = 0.f, vg = 0.f, vo = 0.f;
#pragma unroll
            for (int k2 = 0; k2 < 16; k2++) {
                const float* pk = &part[k2 * 648 + b];
                vi += pk[(0  + jj) * 20];
                vf += pk[(8  + jj) * 20];
                vg += pk[(16 + jj) * 20];
                vo += pk[(24 + jj) * 20];
            }
            vi += bias_s[jj];      vf += bias_s[8 + jj];
            vg += bias_s[16 + jj]; vo += bias_s[24 + jj];
            float ig = sigm_(vi), fg = sigm_(vf);
            float gg = tanh_(vg), og = sigm_(vo);
            float c = fg * c_s[tid] + ig * gg;
            c_s[tid] = c;
            float h = og * tanh_(c);
            int col = jb + jj;
            __stcg(&hbuf[(t + 1) & 1][b * Hdim + col], h);
            if (isA) __stcg(&g_out0[(size_t)(b * Tlen + t) * Hdim + col], h);
            if (t == Tlen - 1) out[lo + b * Hdim + col] = h;
        }

        // stage iw(t+1): A needs nothing; C waits for A step t+1
        if (t + 1 < Tlen) {
            if (!isA) {
                if (lane == 0) while (ld_acq(&g_topA) < 8u * (unsigned)(t + 2)) { }
                __syncwarp();
            }
#pragma unroll
            for (int i = 0; i < 8; i++) {
                int idx = lane + 32 * i, b = idx >> 4, q = idx & 15;
                float4 v = __ldcg((const float4*)&isrc[(size_t)(b * Tlen + t + 1) * Hdim + kwid * 64 + q * 4]);
                *(float4*)&iw[b * 68 + q * 4] = v;
            }
        }
        __syncthreads();

        if (tid == 0 && (isA || t < Tlen - 1))
            arrive_tree(myLeaf, myTop, 8u * (unsigned)(t + 1));
    }
}

// ---------------------------------------------------------------------------
extern "C" void kernel_launch(void* const* d_in, const int* in_sizes, int n_in,
                              void* d_out, int out_size)
{
    const float* x     = (const float*)d_in[0];
    const float* h0    = (const float*)d_in[1];
    const float* c0    = (const float*)d_in[2];
    const float* w_ih0 = (const float*)d_in[3];
    const float* w_hh0 = (const float*)d_in[4];
    const float* b_ih0 = (const float*)d_in[5];
    const float* b_hh0 = (const float*)d_in[6];
    const float* w_ih1 = (const float*)d_in[7];
    const float* w_hh1 = (const float*)d_in[8];
    const float* b_ih1 = (const float*)d_in[9];
    const float* b_hh1 = (const float*)d_in[10];
    float* out = (float*)d_out;

    cudaFuncSetAttribute(lstm_fused, cudaFuncAttributeMaxDynamicSharedMemorySize,
                         SCAN_SMEM);

    reset_sync<<<1, 32>>>();
    lstm_fused<<<NBLK, 256, SCAN_SMEM>>>(x,
                                         w_ih0, w_hh0, b_ih0, b_hh0,
                                         w_ih1, w_hh1, b_ih1, b_hh1,
                                         h0, c0, out);
}